// round 1
// baseline (speedup 1.0000x reference)
#include <cuda_runtime.h>

#define BB 4
#define TT 2048
#define CC 1024
#define HS 64
#define KSPLIT 8
#define SCALE 0.03125f   // C^-0.5 = 1024^-0.5

// Scratch (static device allocations; no cudaMalloc allowed)
__device__ float g_q[BB * TT * HS];
__device__ float g_k[BB * TT * HS];
__device__ float g_v[BB * TT * HS];
__device__ float g_pacc[(size_t)BB * KSPLIT * TT * HS];
__device__ float g_pm[BB * KSPLIT * TT];
__device__ float g_pl[BB * KSPLIT * TT];

// ---------------------------------------------------------------------------
// Kernel 1: QKV projection.  X[8192,1024] @ W[1024,64] for each of Wq/Wk/Wv.
// grid = (128 row-tiles, 3 matrices), 256 threads, BM=64, N=64, BK=32,
// 4x4 register micro-tile per thread.
// ---------------------------------------------------------------------------
__global__ __launch_bounds__(256) void qkv_kernel(
    const float* __restrict__ x,
    const float* __restrict__ Wq,
    const float* __restrict__ Wk,
    const float* __restrict__ Wv) {
    const float* W;
    float* out;
    if (blockIdx.y == 0)      { W = Wq; out = g_q; }
    else if (blockIdx.y == 1) { W = Wk; out = g_k; }
    else                      { W = Wv; out = g_v; }

    __shared__ float Xs[32][64];   // [k][row]  (transposed)
    __shared__ float Ws[32][64];   // [k][col]

    const int tid = threadIdx.x;
    const int tx = tid & 15;       // output-col group
    const int ty = tid >> 4;       // output-row group
    const int row0 = blockIdx.x * 64;

    const int lrow = tid >> 2;     // 0..63  (loader row)
    const int lq   = tid & 3;      // 0..3   (loader float4 slot)
    const int wk   = tid >> 3;     // 0..31  (W loader k)
    const int wf   = tid & 7;      // 0..7   (W loader float4 slot)

    float acc[4][4] = {};

    for (int k0 = 0; k0 < CC; k0 += 32) {
        // Load X tile, transposed into smem
#pragma unroll
        for (int p = 0; p < 2; p++) {
            int f4 = lq + p * 4;
            float4 xv = *reinterpret_cast<const float4*>(
                &x[(size_t)(row0 + lrow) * CC + k0 + f4 * 4]);
            Xs[f4 * 4 + 0][lrow] = xv.x;
            Xs[f4 * 4 + 1][lrow] = xv.y;
            Xs[f4 * 4 + 2][lrow] = xv.z;
            Xs[f4 * 4 + 3][lrow] = xv.w;
        }
        // Load W tile (row-major, coalesced)
#pragma unroll
        for (int p = 0; p < 2; p++) {
            int f4 = wf + p * 8;
            *reinterpret_cast<float4*>(&Ws[wk][f4 * 4]) =
                *reinterpret_cast<const float4*>(&W[(size_t)(k0 + wk) * HS + f4 * 4]);
        }
        __syncthreads();

#pragma unroll
        for (int kk = 0; kk < 32; kk++) {
            float4 a = *reinterpret_cast<float4*>(&Xs[kk][ty * 4]);
            float4 b = *reinterpret_cast<float4*>(&Ws[kk][tx * 4]);
            float av[4] = {a.x, a.y, a.z, a.w};
            float bv[4] = {b.x, b.y, b.z, b.w};
#pragma unroll
            for (int i = 0; i < 4; i++)
#pragma unroll
                for (int j = 0; j < 4; j++)
                    acc[i][j] += av[i] * bv[j];
        }
        __syncthreads();
    }

#pragma unroll
    for (int i = 0; i < 4; i++) {
        float4 o = make_float4(acc[i][0], acc[i][1], acc[i][2], acc[i][3]);
        *reinterpret_cast<float4*>(&out[(size_t)(row0 + ty * 4 + i) * HS + tx * 4]) = o;
    }
}

// ---------------------------------------------------------------------------
// Kernel 2: flash-attention partials with key-split.
// grid = (32 q-tiles, KSPLIT, 4 batches), 256 threads.
// BM=BN=64.  Thread (ty,tx): score micro-tile = rows ty*4..+3 x keys tx*4..+3;
// PV micro-tile = rows ty*4..+3 x dims tx*4..+3.  Online softmax per row,
// partner reduction over the 16 tx lanes (same warp, shfl_xor 1,2,4,8).
// ---------------------------------------------------------------------------
__global__ __launch_bounds__(256) void attn_partial_kernel() {
    const int qtile = blockIdx.x;
    const int split = blockIdx.y;
    const int b     = blockIdx.z;

    const int tid = threadIdx.x;
    const int tx = tid & 15;
    const int ty = tid >> 4;

    __shared__ float Qt[64][64];   // [h][r], pre-scaled
    __shared__ float KtP[64][64];  // [h][j] for K, reused as P_t [j][r]
    __shared__ float Vs[64][64];   // [j][d]

    const int q0 = qtile * 64;
    const int lrow = tid >> 2;
    const int lq   = tid & 3;

    // Load Q tile, transposed + pre-scaled
#pragma unroll
    for (int i = 0; i < 4; i++) {
        int h = lq * 16 + i * 4;
        float4 qv = *reinterpret_cast<const float4*>(
            &g_q[(size_t)(b * TT + q0 + lrow) * HS + h]);
        Qt[h + 0][lrow] = qv.x * SCALE;
        Qt[h + 1][lrow] = qv.y * SCALE;
        Qt[h + 2][lrow] = qv.z * SCALE;
        Qt[h + 3][lrow] = qv.w * SCALE;
    }

    float m_[4], l_[4], acc[4][4];
#pragma unroll
    for (int i = 0; i < 4; i++) {
        m_[i] = -1e30f;
        l_[i] = 0.f;
#pragma unroll
        for (int d = 0; d < 4; d++) acc[i][d] = 0.f;
    }

    for (int kt = split; kt <= qtile; kt += KSPLIT) {
        const int k0 = kt * 64;
        __syncthreads();   // previous tile's P/V reads done; Qt stores covered too

        // Load K (transposed) and V (natural) tiles
#pragma unroll
        for (int i = 0; i < 4; i++) {
            int h = lq * 16 + i * 4;
            float4 kv = *reinterpret_cast<const float4*>(
                &g_k[(size_t)(b * TT + k0 + lrow) * HS + h]);
            KtP[h + 0][lrow] = kv.x;
            KtP[h + 1][lrow] = kv.y;
            KtP[h + 2][lrow] = kv.z;
            KtP[h + 3][lrow] = kv.w;
            float4 vv = *reinterpret_cast<const float4*>(
                &g_v[(size_t)(b * TT + k0 + lrow) * HS + h]);
            *reinterpret_cast<float4*>(&Vs[lrow][h]) = vv;
        }
        __syncthreads();

        // S = (Q*scale) K^T for the micro-tile
        float s[4][4] = {};
#pragma unroll 16
        for (int h = 0; h < 64; h++) {
            float4 a = *reinterpret_cast<float4*>(&Qt[h][ty * 4]);
            float4 bb = *reinterpret_cast<float4*>(&KtP[h][tx * 4]);
            float av[4] = {a.x, a.y, a.z, a.w};
            float bv[4] = {bb.x, bb.y, bb.z, bb.w};
#pragma unroll
            for (int i = 0; i < 4; i++)
#pragma unroll
                for (int j = 0; j < 4; j++)
                    s[i][j] += av[i] * bv[j];
        }

        // Causal mask only on the diagonal tile (k0 == q0 there)
        if (kt == qtile) {
#pragma unroll
            for (int i = 0; i < 4; i++)
#pragma unroll
                for (int j = 0; j < 4; j++)
                    if (tx * 4 + j > ty * 4 + i) s[i][j] = -1e30f;
        }

        // Online softmax per row (reduce across the 16 tx lanes of this warp)
#pragma unroll
        for (int i = 0; i < 4; i++) {
            float tm = fmaxf(fmaxf(s[i][0], s[i][1]), fmaxf(s[i][2], s[i][3]));
#pragma unroll
            for (int o = 1; o < 16; o <<= 1)
                tm = fmaxf(tm, __shfl_xor_sync(0xffffffffu, tm, o));
            float nm  = fmaxf(m_[i], tm);
            float cor = __expf(m_[i] - nm);
            float rs = 0.f;
#pragma unroll
            for (int j = 0; j < 4; j++) {
                s[i][j] = __expf(s[i][j] - nm);
                rs += s[i][j];
            }
#pragma unroll
            for (int o = 1; o < 16; o <<= 1)
                rs += __shfl_xor_sync(0xffffffffu, rs, o);
            l_[i] = l_[i] * cor + rs;
            m_[i] = nm;
#pragma unroll
            for (int d = 0; d < 4; d++) acc[i][d] *= cor;
        }

        __syncthreads();   // done reading K from KtP
        // Store P transposed: P_t[j][r]
#pragma unroll
        for (int j = 0; j < 4; j++) {
            *reinterpret_cast<float4*>(&KtP[tx * 4 + j][ty * 4]) =
                make_float4(s[0][j], s[1][j], s[2][j], s[3][j]);
        }
        __syncthreads();

        // acc += P V
#pragma unroll 16
        for (int j = 0; j < 64; j++) {
            float4 p = *reinterpret_cast<float4*>(&KtP[j][ty * 4]);
            float4 v = *reinterpret_cast<float4*>(&Vs[j][tx * 4]);
            float pv[4] = {p.x, p.y, p.z, p.w};
            float vv[4] = {v.x, v.y, v.z, v.w};
#pragma unroll
            for (int i = 0; i < 4; i++)
#pragma unroll
                for (int d = 0; d < 4; d++)
                    acc[i][d] += pv[i] * vv[d];
        }
    }

    // Write split partials (unnormalized acc + per-row m, l).
    // Idle splits (split > qtile) write m=-1e30, l=0, acc=0 — combine handles it.
    const size_t base = (size_t)(b * KSPLIT + split) * TT + q0;
#pragma unroll
    for (int i = 0; i < 4; i++) {
        int r = ty * 4 + i;
        *reinterpret_cast<float4*>(&g_pacc[(base + r) * HS + tx * 4]) =
            make_float4(acc[i][0], acc[i][1], acc[i][2], acc[i][3]);
        if (tx == 0) {
            g_pm[base + r] = m_[i];
            g_pl[base + r] = l_[i];
        }
    }
}

// ---------------------------------------------------------------------------
// Kernel 3: combine split partials into the final output.
// out[b,q,d] = sum_s exp(m_s - M) acc_s[d] / sum_s exp(m_s - M) l_s
// ---------------------------------------------------------------------------
__global__ __launch_bounds__(256) void combine_kernel(float* __restrict__ out) {
    const int idx = blockIdx.x * 256 + threadIdx.x;  // 0 .. B*T*HS-1
    const int d   = idx & (HS - 1);
    const int row = idx >> 6;          // b*T + q
    const int b   = row >> 11;         // / 2048
    const int q   = row & (TT - 1);

    float M = -1e30f;
#pragma unroll
    for (int s = 0; s < KSPLIT; s++)
        M = fmaxf(M, g_pm[(size_t)(b * KSPLIT + s) * TT + q]);

    float L = 0.f, A = 0.f;
#pragma unroll
    for (int s = 0; s < KSPLIT; s++) {
        size_t pb = (size_t)(b * KSPLIT + s) * TT + q;
        float w = __expf(g_pm[pb] - M);
        L += g_pl[pb] * w;
        A += g_pacc[pb * HS + d] * w;
    }
    out[idx] = A / L;
}

// ---------------------------------------------------------------------------
extern "C" void kernel_launch(void* const* d_in, const int* in_sizes, int n_in,
                              void* d_out, int out_size) {
    const float* x  = (const float*)d_in[0];
    const float* Wq = (const float*)d_in[1];
    const float* Wk = (const float*)d_in[2];
    const float* Wv = (const float*)d_in[3];
    float* out = (float*)d_out;

    // 1) Q,K,V projections
    qkv_kernel<<<dim3((BB * TT) / 64, 3), 256>>>(x, Wq, Wk, Wv);
    // 2) Split-K causal flash attention partials
    attn_partial_kernel<<<dim3(TT / 64, KSPLIT, BB), 256>>>();
    // 3) Combine
    combine_kernel<<<(BB * TT * HS) / 256, 256>>>(out);
}